// round 4
// baseline (speedup 1.0000x reference)
#include <cuda_runtime.h>
#include <cstdint>

constexpr int GRID  = 1184;   // 148 SMs * 8
constexpr int BLOCK = 256;
constexpr int UNROLL = 8;     // 8 outstanding LDG.128 per thread

// Per-block partial sums of squares. Fully overwritten every replay.
__device__ float g_partials[GRID];

struct TensorSet {
    const float4* p[5];
    float4*       o[5];   // output slice base (concatenated layout), vec4 units
    long          n[5];   // vec4 element counts
};

__device__ __forceinline__ float dot4_acc(float4 v, float a) {
    a = fmaf(v.x, v.x, a);
    a = fmaf(v.y, v.y, a);
    a = fmaf(v.z, v.z, a);
    a = fmaf(v.w, v.w, a);
    return a;
}

// Pass 1: sum of squares -> per-block partials.
// Contiguous per-block chunk: block walks 4KB/iter of contiguous DRAM.
__global__ void __launch_bounds__(BLOCK) reduce_sumsq_kernel(TensorSet ts) {
    float a[UNROLL];
    #pragma unroll
    for (int k = 0; k < UNROLL; ++k) a[k] = 0.f;

    #pragma unroll
    for (int t = 0; t < 5; ++t) {
        const float4* __restrict__ p = ts.p[t];
        const long n = ts.n[t];
        const long chunk = (n + GRID - 1) / GRID;
        const long start = (long)blockIdx.x * chunk;
        const long end   = (start + chunk < n) ? (start + chunk) : n;

        long i = start + threadIdx.x;
        for (; i + (UNROLL - 1) * BLOCK < end; i += UNROLL * BLOCK) {
            float4 v[UNROLL];
            #pragma unroll
            for (int k = 0; k < UNROLL; ++k) v[k] = p[i + k * BLOCK];
            #pragma unroll
            for (int k = 0; k < UNROLL; ++k) a[k] = dot4_acc(v[k], a[k]);
        }
        for (; i < end; i += BLOCK)
            a[0] = dot4_acc(p[i], a[0]);
    }

    float acc = 0.f;
    #pragma unroll
    for (int k = 0; k < UNROLL; ++k) acc += a[k];

    #pragma unroll
    for (int off = 16; off > 0; off >>= 1)
        acc += __shfl_xor_sync(0xFFFFFFFFu, acc, off);

    __shared__ float warp_sums[BLOCK / 32];
    const int lane = threadIdx.x & 31;
    const int wid  = threadIdx.x >> 5;
    if (lane == 0) warp_sums[wid] = acc;
    __syncthreads();

    if (wid == 0) {
        float s = (lane < (BLOCK >> 5)) ? warp_sums[lane] : 0.0f;
        #pragma unroll
        for (int off = 4; off > 0; off >>= 1)
            s += __shfl_xor_sync(0xFFFFFFFFu, s, off);
        if (lane == 0)
            g_partials[blockIdx.x] = s;
    }
}

// Pass 2: every block redundantly reduces the 1184 partials (deterministic,
// fixed order -> identical scale in every block; the 8KB array is L2-broadcast
// and free under DRAM-bound streaming), then streams scaled output.
__global__ void __launch_bounds__(BLOCK) scale_kernel(TensorSet ts) {
    // --- reduce partials in double (precision + determinism) ---
    double d = 0.0;
    for (int i = threadIdx.x; i < GRID; i += BLOCK)
        d += (double)g_partials[i];

    #pragma unroll
    for (int off = 16; off > 0; off >>= 1)
        d += __shfl_xor_sync(0xFFFFFFFFu, d, off);

    __shared__ double warp_sums_d[BLOCK / 32];
    __shared__ float  s_scale;
    const int lane = threadIdx.x & 31;
    const int wid  = threadIdx.x >> 5;
    if (lane == 0) warp_sums_d[wid] = d;
    __syncthreads();
    if (wid == 0) {
        double s = (lane < (BLOCK >> 5)) ? warp_sums_d[lane] : 0.0;
        #pragma unroll
        for (int off = 4; off > 0; off >>= 1)
            s += __shfl_xor_sync(0xFFFFFFFFu, s, off);
        if (lane == 0) {
            float norm = sqrtf((float)s);
            s_scale = (norm > 1.0f) ? (1.0f / (norm + 1e-6f)) : 1.0f;
        }
    }
    __syncthreads();
    const float scale = s_scale;

    // --- streaming scale, contiguous per-block chunks ---
    #pragma unroll
    for (int t = 0; t < 5; ++t) {
        const float4* __restrict__ p = ts.p[t];
        float4* __restrict__ o = ts.o[t];
        const long n = ts.n[t];
        const long chunk = (n + GRID - 1) / GRID;
        const long start = (long)blockIdx.x * chunk;
        const long end   = (start + chunk < n) ? (start + chunk) : n;

        long i = start + threadIdx.x;
        for (; i + (UNROLL - 1) * BLOCK < end; i += UNROLL * BLOCK) {
            float4 v[UNROLL];
            #pragma unroll
            for (int k = 0; k < UNROLL; ++k) v[k] = __ldcs(p + i + k * BLOCK);
            #pragma unroll
            for (int k = 0; k < UNROLL; ++k) {
                v[k].x *= scale; v[k].y *= scale;
                v[k].z *= scale; v[k].w *= scale;
            }
            #pragma unroll
            for (int k = 0; k < UNROLL; ++k) __stcs(o + i + k * BLOCK, v[k]);
        }
        for (; i < end; i += BLOCK) {
            float4 v = __ldcs(p + i);
            v.x *= scale; v.y *= scale; v.z *= scale; v.w *= scale;
            __stcs(o + i, v);
        }
    }
}

extern "C" void kernel_launch(void* const* d_in, const int* in_sizes, int n_in,
                              void* d_out, int out_size) {
    TensorSet ts;
    long off = 0;
    float* out = (float*)d_out;
    for (int t = 0; t < 5; ++t) {
        ts.p[t] = (const float4*)d_in[t];
        ts.o[t] = (float4*)(out + off);
        ts.n[t] = (long)in_sizes[t] / 4;   // all counts divisible by 4
        off += (long)in_sizes[t];
    }

    reduce_sumsq_kernel<<<GRID, BLOCK>>>(ts);
    scale_kernel<<<GRID, BLOCK>>>(ts);
}

// round 6
// speedup vs baseline: 1.0588x; 1.0588x over previous
#include <cuda_runtime.h>
#include <cstdint>

constexpr int GRID   = 740;    // 148 SMs * 5 blocks -> exactly one wave at 48 regs
constexpr int BLOCK  = 256;
constexpr int UNROLL = 8;
constexpr long TAIL_VEC4 = 6L * 1024 * 1024;  // 96 MB L2-resident handoff region

// Per-block partial sums of squares. Fully overwritten every replay.
__device__ float g_partials[GRID];

struct TensorSet {
    const float4* p[5];
    float4*       o[5];   // output slice base (concatenated layout), vec4 units
    long          n[5];   // vec4 element counts
};

__device__ __forceinline__ float dot4_acc(float4 v, float a) {
    a = fmaf(v.x, v.x, a);
    a = fmaf(v.y, v.y, a);
    a = fmaf(v.z, v.z, a);
    a = fmaf(v.w, v.w, a);
    return a;
}

// Grid-stride sum-of-squares over [lo, hi). STREAM: evict-first loads.
template <bool STREAM>
__device__ __forceinline__ void sweep_reduce(const float4* __restrict__ p,
                                             long lo, long hi, long base,
                                             long stride, float a[UNROLL]) {
    long i = lo + base;
    for (; i + (UNROLL - 1) * stride < hi; i += UNROLL * stride) {
        float4 v[UNROLL];
        #pragma unroll
        for (int k = 0; k < UNROLL; ++k)
            v[k] = STREAM ? __ldcs(p + i + k * stride) : p[i + k * stride];
        #pragma unroll
        for (int k = 0; k < UNROLL; ++k) a[k] = dot4_acc(v[k], a[k]);
    }
    for (; i < hi; i += stride)
        a[0] = dot4_acc(STREAM ? __ldcs(p + i) : p[i], a[0]);
}

// Grid-stride scale+store over [lo, hi). STREAM_LD: evict-first loads.
template <bool STREAM_LD>
__device__ __forceinline__ void sweep_scale(const float4* __restrict__ p,
                                            float4* __restrict__ o,
                                            long lo, long hi, long base,
                                            long stride, float scale) {
    long i = lo + base;
    for (; i + (UNROLL - 1) * stride < hi; i += UNROLL * stride) {
        float4 v[UNROLL];
        #pragma unroll
        for (int k = 0; k < UNROLL; ++k)
            v[k] = STREAM_LD ? __ldcs(p + i + k * stride) : p[i + k * stride];
        #pragma unroll
        for (int k = 0; k < UNROLL; ++k) {
            v[k].x *= scale; v[k].y *= scale;
            v[k].z *= scale; v[k].w *= scale;
        }
        #pragma unroll
        for (int k = 0; k < UNROLL; ++k) __stcs(o + i + k * stride, v[k]);
    }
    for (; i < hi; i += stride) {
        float4 v = STREAM_LD ? __ldcs(p + i) : p[i];
        v.x *= scale; v.y *= scale; v.z *= scale; v.w *= scale;
        __stcs(o + i, v);
    }
}

// Pass 1: tensors 0..3, then t4[D4, n4), then t4[0, D4) LAST with evict-normal
// loads -> that 96MB region stays resident in L2 for pass 2.
__global__ void __launch_bounds__(BLOCK, 5) reduce_sumsq_kernel(TensorSet ts) {
    const long stride = (long)GRID * BLOCK;
    const long base   = (long)blockIdx.x * BLOCK + threadIdx.x;

    float a[UNROLL];
    #pragma unroll
    for (int k = 0; k < UNROLL; ++k) a[k] = 0.f;

    #pragma unroll
    for (int t = 0; t < 4; ++t)
        sweep_reduce<true>(ts.p[t], 0, ts.n[t], base, stride, a);

    const long n4 = ts.n[4];
    const long D4 = (TAIL_VEC4 < n4) ? TAIL_VEC4 : n4;
    sweep_reduce<true >(ts.p[4], D4, n4, base, stride, a);
    sweep_reduce<false>(ts.p[4], 0,  D4, base, stride, a);  // read last, keep in L2

    float acc = 0.f;
    #pragma unroll
    for (int k = 0; k < UNROLL; ++k) acc += a[k];

    #pragma unroll
    for (int off = 16; off > 0; off >>= 1)
        acc += __shfl_xor_sync(0xFFFFFFFFu, acc, off);

    __shared__ float warp_sums[BLOCK / 32];
    const int lane = threadIdx.x & 31;
    const int wid  = threadIdx.x >> 5;
    if (lane == 0) warp_sums[wid] = acc;
    __syncthreads();

    if (wid == 0) {
        float s = (lane < (BLOCK >> 5)) ? warp_sums[lane] : 0.0f;
        #pragma unroll
        for (int off = 4; off > 0; off >>= 1)
            s += __shfl_xor_sync(0xFFFFFFFFu, s, off);
        if (lane == 0)
            g_partials[blockIdx.x] = s;
    }
}

// Pass 2: reduce partials (redundantly per block, fixed order -> deterministic,
// identical scale everywhere; 3KB array is L2-broadcast), then stream scaled
// output: t4[0, D4) FIRST (L2 hits from pass 1), then t4[D4, n4), then t0..t3.
__global__ void __launch_bounds__(BLOCK, 5) scale_kernel(TensorSet ts) {
    double d = 0.0;
    for (int i = threadIdx.x; i < GRID; i += BLOCK)
        d += (double)g_partials[i];

    #pragma unroll
    for (int off = 16; off > 0; off >>= 1)
        d += __shfl_xor_sync(0xFFFFFFFFu, d, off);

    __shared__ double warp_sums_d[BLOCK / 32];
    __shared__ float  s_scale;
    const int lane = threadIdx.x & 31;
    const int wid  = threadIdx.x >> 5;
    if (lane == 0) warp_sums_d[wid] = d;
    __syncthreads();
    if (wid == 0) {
        double s = (lane < (BLOCK >> 5)) ? warp_sums_d[lane] : 0.0;
        #pragma unroll
        for (int off = 4; off > 0; off >>= 1)
            s += __shfl_xor_sync(0xFFFFFFFFu, s, off);
        if (lane == 0) {
            float norm = sqrtf((float)s);
            s_scale = (norm > 1.0f) ? (1.0f / (norm + 1e-6f)) : 1.0f;
        }
    }
    __syncthreads();
    const float scale = s_scale;

    const long stride = (long)GRID * BLOCK;
    const long base   = (long)blockIdx.x * BLOCK + threadIdx.x;

    const long n4 = ts.n[4];
    const long D4 = (TAIL_VEC4 < n4) ? TAIL_VEC4 : n4;
    sweep_scale<false>(ts.p[4], ts.o[4], 0,  D4, base, stride, scale);  // L2 hits
    sweep_scale<true >(ts.p[4], ts.o[4], D4, n4, base, stride, scale);

    #pragma unroll
    for (int t = 0; t < 4; ++t)
        sweep_scale<true>(ts.p[t], ts.o[t], 0, ts.n[t], base, stride, scale);
}

extern "C" void kernel_launch(void* const* d_in, const int* in_sizes, int n_in,
                              void* d_out, int out_size) {
    TensorSet ts;
    long off = 0;
    float* out = (float*)d_out;
    for (int t = 0; t < 5; ++t) {
        ts.p[t] = (const float4*)d_in[t];
        ts.o[t] = (float4*)(out + off);
        ts.n[t] = (long)in_sizes[t] / 4;   // all counts divisible by 4
        off += (long)in_sizes[t];
    }

    reduce_sumsq_kernel<<<GRID, BLOCK>>>(ts);
    scale_kernel<<<GRID, BLOCK>>>(ts);
}